// round 10
// baseline (speedup 1.0000x reference)
#include <cuda_runtime.h>
#include <math.h>

// Problem constants (fixed by the reference)
constexpr int Bc = 8, Cc = 768, NHc = 12, HDc = 64;
constexpr int Hc = 64, Wc = 64, HWc = 4096, Nc = 4097;   // N = NC + H*W, NC = 1
constexpr int Mtot = Bc * Nc;                            // 32776
constexpr float SCALEc = 0.125f;                         // HD^-0.5
#define NEG_C (-10000.0f)

// Scratch (device globals — allocation-free per harness rules)
__device__ float g_q[(size_t)Bc * NHc * Nc * HDc];
__device__ float g_k[(size_t)Bc * NHc * Nc * HDc];
__device__ float g_v[(size_t)Bc * NHc * Nc * HDc];
__device__ float g_y[(size_t)Bc * Nc * Cc];   // row 0 per batch = x_cls, rows 1.. = x_img
__device__ float g_vcls[Bc * Cc];

// ---------------------------------------------------------------------------
// Tiled SGEMM: C[M x NCOLS] = A[M x 768] @ B[768 x NCOLS]
//   EPI=1: scatter into g_q/g_k/g_v with layout [b, h, n, d]
//   EPI=0: C = acc + bias  (proj)
//   AGY:   A comes from the g_y device global instead of the pointer arg
// 128x128 block tile, BK=16, 256 threads, 8x8 per thread.
// ---------------------------------------------------------------------------
template <int NCOLS, int EPI, bool AGY>
__global__ __launch_bounds__(256)
void sgemm(const float* __restrict__ Ain, const float* __restrict__ Bm,
           float* __restrict__ Cm, const float* __restrict__ bias) {
    const float* A = AGY ? (const float*)g_y : Ain;
    __shared__ float As[16][128];   // transposed: As[k][m]
    __shared__ float Bs[16][128];
    const int tid = threadIdx.x;
    const int m0 = blockIdx.y * 128;
    const int n0 = blockIdx.x * 128;
    const int ty = tid >> 4, tx = tid & 15;

    float acc[8][8];
#pragma unroll
    for (int i = 0; i < 8; i++)
#pragma unroll
        for (int j = 0; j < 8; j++) acc[i][j] = 0.f;

    for (int k0 = 0; k0 < Cc; k0 += 16) {
#pragma unroll
        for (int l = 0; l < 2; l++) {
            int idx = tid + l * 256;
            int row = idx >> 2;
            int kq = (idx & 3) << 2;
            int gr = m0 + row;
            float4 va = make_float4(0.f, 0.f, 0.f, 0.f);
            if (gr < Mtot)
                va = *reinterpret_cast<const float4*>(&A[(size_t)gr * Cc + k0 + kq]);
            As[kq + 0][row] = va.x;
            As[kq + 1][row] = va.y;
            As[kq + 2][row] = va.z;
            As[kq + 3][row] = va.w;
        }
#pragma unroll
        for (int l = 0; l < 2; l++) {
            int idx = tid + l * 256;
            int row = idx >> 5;
            int cq = (idx & 31) << 2;
            *reinterpret_cast<float4*>(&Bs[row][cq]) =
                *reinterpret_cast<const float4*>(&Bm[(size_t)(k0 + row) * NCOLS + n0 + cq]);
        }
        __syncthreads();
#pragma unroll
        for (int kk = 0; kk < 16; kk++) {
            float4 a0 = *reinterpret_cast<const float4*>(&As[kk][ty * 8]);
            float4 a1 = *reinterpret_cast<const float4*>(&As[kk][ty * 8 + 4]);
            float4 b0 = *reinterpret_cast<const float4*>(&Bs[kk][tx * 8]);
            float4 b1 = *reinterpret_cast<const float4*>(&Bs[kk][tx * 8 + 4]);
            float a[8] = {a0.x, a0.y, a0.z, a0.w, a1.x, a1.y, a1.z, a1.w};
            float b[8] = {b0.x, b0.y, b0.z, b0.w, b1.x, b1.y, b1.z, b1.w};
#pragma unroll
            for (int i = 0; i < 8; i++)
#pragma unroll
                for (int j = 0; j < 8; j++)
                    acc[i][j] = fmaf(a[i], b[j], acc[i][j]);
        }
        __syncthreads();
    }

    if (EPI == 1) {
        // All 8 columns of a thread share the same (which, head): c0 % 64 <= 56.
        const int c0 = n0 + tx * 8;
        const int which = c0 / Cc;
        const int within0 = c0 - which * Cc;
        const int h = within0 >> 6;
        const int d0 = within0 & 63;
        float* dst = (which == 0) ? g_q : (which == 1) ? g_k : g_v;
#pragma unroll
        for (int i = 0; i < 8; i++) {
            int r = m0 + ty * 8 + i;
            if (r >= Mtot) continue;
            int bb = r / Nc;
            int nn = r - bb * Nc;
            size_t rowoff = (((size_t)bb * NHc + h) * Nc + nn) * HDc + d0;
#pragma unroll
            for (int j = 0; j < 8; j++) dst[rowoff + j] = acc[i][j];
        }
    } else {
        const int c0 = n0 + tx * 8;
#pragma unroll
        for (int i = 0; i < 8; i++) {
            int r = m0 + ty * 8 + i;
            if (r >= Mtot) continue;
#pragma unroll
            for (int j = 0; j < 8; j++)
                Cm[(size_t)r * NCOLS + c0 + j] = acc[i][j] + bias[c0 + j];
        }
    }
}

// ---------------------------------------------------------------------------
// Window attention: one block per (b, window, head). 64 tokens x 64 dims.
// mask collapses to tok_i * tok_j (mask is a channel-broadcast of tok).
// smem: X (q, later v), Y (k, later P). 4x4 register blocking, 256 threads.
// ---------------------------------------------------------------------------
__global__ __launch_bounds__(256)
void win_attn(const float* __restrict__ mask) {
    __shared__ float X[64][65];
    __shared__ float Y[64][65];
    __shared__ float tok[64];
    const int bid = blockIdx.x;
    const int h = bid % NHc;
    const int win = (bid / NHc) & 63;
    const int b = bid / (NHc * 64);
    const int wy = win >> 3, wx = win & 7;
    const int tid = threadIdx.x;
    const size_t base = ((size_t)b * NHc + h) * Nc;

    float vreg[4][4];
#pragma unroll
    for (int l = 0; l < 4; l++) {
        int idx = tid + l * 256;
        int t = idx >> 4;
        int dq = (idx & 15) << 2;
        int iy = t >> 3, ix = t & 7;
        int nimg = (wy * 8 + iy) * Wc + wx * 8 + ix;
        size_t off = (base + 1 + nimg) * HDc + dq;
        float4 vq = *reinterpret_cast<const float4*>(&g_q[off]);
        float4 vk = *reinterpret_cast<const float4*>(&g_k[off]);
        float4 vv = *reinterpret_cast<const float4*>(&g_v[off]);
        X[t][dq] = vq.x; X[t][dq + 1] = vq.y; X[t][dq + 2] = vq.z; X[t][dq + 3] = vq.w;
        Y[t][dq] = vk.x; Y[t][dq + 1] = vk.y; Y[t][dq + 2] = vk.z; Y[t][dq + 3] = vk.w;
        vreg[l][0] = vv.x; vreg[l][1] = vv.y; vreg[l][2] = vv.z; vreg[l][3] = vv.w;
    }
    if (tid < 64) {
        int iy = tid >> 3, ix = tid & 7;
        int nimg = (wy * 8 + iy) * Wc + wx * 8 + ix;
        tok[tid] = mask[((size_t)b * HWc + nimg) * Cc];
    }
    __syncthreads();

    const int rg = tid >> 4, cg = tid & 15;
    const int i0 = rg * 4, j0 = cg * 4;
    float s[4][4];
#pragma unroll
    for (int ii = 0; ii < 4; ii++)
#pragma unroll
        for (int jj = 0; jj < 4; jj++) s[ii][jj] = 0.f;

#pragma unroll 8
    for (int d = 0; d < 64; d++) {
        float a[4], bb[4];
#pragma unroll
        for (int ii = 0; ii < 4; ii++) a[ii] = X[i0 + ii][d];
#pragma unroll
        for (int jj = 0; jj < 4; jj++) bb[jj] = Y[j0 + jj][d];
#pragma unroll
        for (int ii = 0; ii < 4; ii++)
#pragma unroll
            for (int jj = 0; jj < 4; jj++)
                s[ii][jj] = fmaf(a[ii], bb[jj], s[ii][jj]);
    }
    float ti[4], tj[4];
#pragma unroll
    for (int ii = 0; ii < 4; ii++) ti[ii] = tok[i0 + ii];
#pragma unroll
    for (int jj = 0; jj < 4; jj++) tj[jj] = tok[j0 + jj];
    __syncthreads();  // all reads of X(q), Y(k) done

    // stash V into X
#pragma unroll
    for (int l = 0; l < 4; l++) {
        int idx = tid + l * 256;
        int t = idx >> 4;
        int dq = (idx & 15) << 2;
        X[t][dq] = vreg[l][0]; X[t][dq + 1] = vreg[l][1];
        X[t][dq + 2] = vreg[l][2]; X[t][dq + 3] = vreg[l][3];
    }
    // softmax per row (16 threads per row; lanes form aligned 16-groups in a warp)
#pragma unroll
    for (int ii = 0; ii < 4; ii++) {
        float mx = -1e30f;
#pragma unroll
        for (int jj = 0; jj < 4; jj++) {
            float val = (ti[ii] * tj[jj] == 0.f) ? NEG_C : s[ii][jj] * SCALEc;
            s[ii][jj] = val;
            mx = fmaxf(mx, val);
        }
#pragma unroll
        for (int o = 8; o >= 1; o >>= 1)
            mx = fmaxf(mx, __shfl_xor_sync(0xffffffffu, mx, o));
        float sum = 0.f;
#pragma unroll
        for (int jj = 0; jj < 4; jj++) {
            float e = expf(s[ii][jj] - mx);
            s[ii][jj] = e;
            sum += e;
        }
#pragma unroll
        for (int o = 8; o >= 1; o >>= 1)
            sum += __shfl_xor_sync(0xffffffffu, sum, o);
        float inv = 1.f / sum;
#pragma unroll
        for (int jj = 0; jj < 4; jj++) Y[i0 + ii][j0 + jj] = s[ii][jj] * inv;
    }
    __syncthreads();

    // O = P @ V
    float o[4][4];
#pragma unroll
    for (int ii = 0; ii < 4; ii++)
#pragma unroll
        for (int jj = 0; jj < 4; jj++) o[ii][jj] = 0.f;
#pragma unroll 8
    for (int k = 0; k < 64; k++) {
        float a[4], bb[4];
#pragma unroll
        for (int ii = 0; ii < 4; ii++) a[ii] = Y[i0 + ii][k];
#pragma unroll
        for (int jj = 0; jj < 4; jj++) bb[jj] = X[k][j0 + jj];
#pragma unroll
        for (int ii = 0; ii < 4; ii++)
#pragma unroll
            for (int jj = 0; jj < 4; jj++)
                o[ii][jj] = fmaf(a[ii], bb[jj], o[ii][jj]);
    }
#pragma unroll
    for (int ii = 0; ii < 4; ii++) {
        int i = i0 + ii;
        int iy = i >> 3, ix = i & 7;
        int nimg = (wy * 8 + iy) * Wc + wx * 8 + ix;
        float4 w = make_float4(o[ii][0], o[ii][1], o[ii][2], o[ii][3]);
        *reinterpret_cast<float4*>(&g_y[((size_t)b * Nc + 1 + nimg) * Cc + h * 64 + j0]) = w;
    }
}

// ---------------------------------------------------------------------------
// Global (cls) attention: one block per (b, h). 4096 keys, HD=64.
// am_g = tok[n] * global_mask[b,h,0,n].
// ---------------------------------------------------------------------------
__global__ __launch_bounds__(256)
void cls_attn(const float* __restrict__ mask, const float* __restrict__ gmask) {
    __shared__ float qsh[64];
    __shared__ float sc[HWc];
    __shared__ float red[256];
    __shared__ float part[4][64];
    const int b = blockIdx.x / NHc;
    const int h = blockIdx.x % NHc;
    const int tid = threadIdx.x;
    const size_t base = ((size_t)b * NHc + h) * Nc;
    if (tid < 64) qsh[tid] = g_q[base * HDc + tid];
    __syncthreads();

    float lmax = -1e30f;
    for (int rep = 0; rep < 16; rep++) {
        int n = rep * 256 + tid;
        const float* kr = &g_k[(base + 1 + n) * HDc];
        float acc = 0.f;
#pragma unroll
        for (int d = 0; d < 64; d++) acc = fmaf(qsh[d], kr[d], acc);
        float tokn = mask[((size_t)b * HWc + n) * Cc];
        float gm = gmask[((size_t)b * NHc + h) * HWc + n];
        float s = (tokn * gm == 0.f) ? NEG_C : acc * SCALEc;
        sc[n] = s;
        lmax = fmaxf(lmax, s);
    }
    red[tid] = lmax;
    __syncthreads();
    for (int st = 128; st > 0; st >>= 1) {
        if (tid < st) red[tid] = fmaxf(red[tid], red[tid + st]);
        __syncthreads();
    }
    float mx = red[0];
    __syncthreads();
    float lsum = 0.f;
    for (int rep = 0; rep < 16; rep++) {
        int n = rep * 256 + tid;
        float e = expf(sc[n] - mx);
        sc[n] = e;
        lsum += e;
    }
    red[tid] = lsum;
    __syncthreads();
    for (int st = 128; st > 0; st >>= 1) {
        if (tid < st) red[tid] += red[tid + st];
        __syncthreads();
    }
    float inv = 1.f / red[0];

    int d = tid & 63, g = tid >> 6;
    float acc = 0.f;
    for (int n = g; n < HWc; n += 4)
        acc = fmaf(sc[n], g_v[(base + 1 + n) * HDc + d], acc);
    part[g][d] = acc;
    __syncthreads();
    if (tid < 64)
        g_y[(size_t)b * Nc * Cc + h * 64 + tid] =
            (part[0][tid] + part[1][tid] + part[2][tid] + part[3][tid]) * inv;
}

// ---------------------------------------------------------------------------
// v_cls = x_cls @ kv_global_w[:, 768:1536]   (k_cls is dead: softmax over NC=1 == 1)
// ---------------------------------------------------------------------------
__global__ __launch_bounds__(256)
void vcls_gemm(const float* __restrict__ kvw) {
    __shared__ float xc[768];
    const int b = blockIdx.x;
    const int tid = threadIdx.x;
#pragma unroll
    for (int l = 0; l < 3; l++)
        xc[tid + l * 256] = g_y[(size_t)b * Nc * Cc + tid + l * 256];
    __syncthreads();
    float acc[3] = {0.f, 0.f, 0.f};
    for (int k = 0; k < 768; k++) {
        float xv = xc[k];
        const float* wr = &kvw[(size_t)k * 1536 + 768];
#pragma unroll
        for (int l = 0; l < 3; l++)
            acc[l] = fmaf(xv, wr[tid + l * 256], acc[l]);
    }
#pragma unroll
    for (int l = 0; l < 3; l++)
        g_vcls[b * Cc + tid + l * 256] = acc[l];
}

// x_img += v_cls broadcast (the entire attn_b stage, since softmax over NC=1 is 1)
__global__ void add_vcls_kernel() {
    constexpr size_t total = (size_t)Bc * HWc * Cc;
    size_t idx = (size_t)blockIdx.x * blockDim.x + threadIdx.x;
    if (idx >= total) return;
    int c = (int)(idx % Cc);
    size_t rem = idx / Cc;
    int n = (int)(rem % HWc);
    int b = (int)(rem / HWc);
    g_y[((size_t)b * Nc + 1 + n) * Cc + c] += g_vcls[b * Cc + c];
}

// ---------------------------------------------------------------------------
extern "C" void kernel_launch(void* const* d_in, const int* in_sizes, int n_in,
                              void* d_out, int out_size) {
    (void)in_sizes; (void)n_in; (void)out_size;
    const float* x      = (const float*)d_in[0];
    const float* mask   = (const float*)d_in[1];
    const float* gmask  = (const float*)d_in[2];
    const float* qkv_w  = (const float*)d_in[3];
    const float* kv_w   = (const float*)d_in[4];
    const float* proj_w = (const float*)d_in[5];
    const float* proj_b = (const float*)d_in[6];
    float* out = (float*)d_out;

    // 1) qkv = x @ qkv_w, scattered into head-major q/k/v
    dim3 g1(2304 / 128, (Mtot + 127) / 128);
    sgemm<2304, 1, false><<<g1, 256>>>(x, qkv_w, nullptr, nullptr);

    // 2) window attention -> g_y image rows
    win_attn<<<Bc * 64 * NHc, 256>>>(mask);

    // 3) cls global attention -> g_y row 0 per batch
    cls_attn<<<Bc * NHc, 256>>>(mask, gmask);

    // 4) v_cls = x_cls @ kv_global_w[:,768:]
    vcls_gemm<<<Bc, 256>>>(kv_w);

    // 5) x_img += v_cls
    constexpr size_t total = (size_t)Bc * HWc * Cc;
    add_vcls_kernel<<<(unsigned)((total + 255) / 256), 256>>>();

    // 6) out = y @ proj_w + proj_b
    dim3 g2(768 / 128, (Mtot + 127) / 128);
    sgemm<768, 0, true><<<g2, 256>>>(nullptr, proj_w, out, proj_b);
}

// round 11
// speedup vs baseline: 1.6082x; 1.6082x over previous
#include <cuda_runtime.h>
#include <math.h>

// Problem constants (fixed by the reference)
constexpr int Bc = 8, Cc = 768, NHc = 12, HDc = 64;
constexpr int Hc = 64, Wc = 64, HWc = 4096, Nc = 4097;   // N = NC + H*W, NC = 1
constexpr int Mtot = Bc * Nc;                            // 32776
constexpr float SCALEc = 0.125f;                         // HD^-0.5
#define NEG_C (-10000.0f)

// Scratch (device globals — allocation-free per harness rules)
__device__ float g_q[(size_t)Bc * NHc * Nc * HDc];
__device__ float g_k[(size_t)Bc * NHc * Nc * HDc];
__device__ float g_v[(size_t)Bc * NHc * Nc * HDc];
__device__ float g_y[(size_t)Bc * Nc * Cc];   // row 0 per batch = x_cls, rows 1.. = x_img
__device__ float g_vcls[Bc * Cc];

// ---------------------------------------------------------------------------
// Tiled SGEMM: C[M x NCOLS] = A[M x 768] @ B[768 x NCOLS]
//   EPI=1: scatter into g_q/g_k/g_v with layout [b, h, n, d]
//   EPI=0: C = acc + bias  (proj)
//   AGY:   A comes from the g_y device global instead of the pointer arg
// 128x128 block tile, BK=16, 256 threads, 8x8 per thread.
// ---------------------------------------------------------------------------
template <int NCOLS, int EPI, bool AGY>
__global__ __launch_bounds__(256)
void sgemm(const float* __restrict__ Ain, const float* __restrict__ Bm,
           float* __restrict__ Cm, const float* __restrict__ bias) {
    const float* A = AGY ? (const float*)g_y : Ain;
    __shared__ float As[16][128];   // transposed: As[k][m]
    __shared__ float Bs[16][128];
    const int tid = threadIdx.x;
    const int m0 = blockIdx.y * 128;
    const int n0 = blockIdx.x * 128;
    const int ty = tid >> 4, tx = tid & 15;

    float acc[8][8];
#pragma unroll
    for (int i = 0; i < 8; i++)
#pragma unroll
        for (int j = 0; j < 8; j++) acc[i][j] = 0.f;

    for (int k0 = 0; k0 < Cc; k0 += 16) {
#pragma unroll
        for (int l = 0; l < 2; l++) {
            int idx = tid + l * 256;
            int row = idx >> 2;
            int kq = (idx & 3) << 2;
            int gr = m0 + row;
            float4 va = make_float4(0.f, 0.f, 0.f, 0.f);
            if (gr < Mtot)
                va = *reinterpret_cast<const float4*>(&A[(size_t)gr * Cc + k0 + kq]);
            As[kq + 0][row] = va.x;
            As[kq + 1][row] = va.y;
            As[kq + 2][row] = va.z;
            As[kq + 3][row] = va.w;
        }
#pragma unroll
        for (int l = 0; l < 2; l++) {
            int idx = tid + l * 256;
            int row = idx >> 5;
            int cq = (idx & 31) << 2;
            *reinterpret_cast<float4*>(&Bs[row][cq]) =
                *reinterpret_cast<const float4*>(&Bm[(size_t)(k0 + row) * NCOLS + n0 + cq]);
        }
        __syncthreads();
#pragma unroll
        for (int kk = 0; kk < 16; kk++) {
            float4 a0 = *reinterpret_cast<const float4*>(&As[kk][ty * 8]);
            float4 a1 = *reinterpret_cast<const float4*>(&As[kk][ty * 8 + 4]);
            float4 b0 = *reinterpret_cast<const float4*>(&Bs[kk][tx * 8]);
            float4 b1 = *reinterpret_cast<const float4*>(&Bs[kk][tx * 8 + 4]);
            float a[8] = {a0.x, a0.y, a0.z, a0.w, a1.x, a1.y, a1.z, a1.w};
            float b[8] = {b0.x, b0.y, b0.z, b0.w, b1.x, b1.y, b1.z, b1.w};
#pragma unroll
            for (int i = 0; i < 8; i++)
#pragma unroll
                for (int j = 0; j < 8; j++)
                    acc[i][j] = fmaf(a[i], b[j], acc[i][j]);
        }
        __syncthreads();
    }

    if (EPI == 1) {
        // All 8 columns of a thread share the same (which, head): c0 % 64 <= 56.
        const int c0 = n0 + tx * 8;
        const int which = c0 / Cc;
        const int within0 = c0 - which * Cc;
        const int h = within0 >> 6;
        const int d0 = within0 & 63;
        float* dst = (which == 0) ? g_q : (which == 1) ? g_k : g_v;
#pragma unroll
        for (int i = 0; i < 8; i++) {
            int r = m0 + ty * 8 + i;
            if (r >= Mtot) continue;
            int bb = r / Nc;
            int nn = r - bb * Nc;
            size_t rowoff = (((size_t)bb * NHc + h) * Nc + nn) * HDc + d0;
#pragma unroll
            for (int j = 0; j < 8; j++) dst[rowoff + j] = acc[i][j];
        }
    } else {
        const int c0 = n0 + tx * 8;
#pragma unroll
        for (int i = 0; i < 8; i++) {
            int r = m0 + ty * 8 + i;
            if (r >= Mtot) continue;
#pragma unroll
            for (int j = 0; j < 8; j++)
                Cm[(size_t)r * NCOLS + c0 + j] = acc[i][j] + bias[c0 + j];
        }
    }
}

// ---------------------------------------------------------------------------
// Window attention: one block per (b, window, head). 64 tokens x 64 dims.
// mask collapses to tok_i * tok_j (mask is a channel-broadcast of tok).
// smem: X (q, later v), Y (k, later P). 4x4 register blocking, 256 threads.
// ---------------------------------------------------------------------------
__global__ __launch_bounds__(256)
void win_attn(const float* __restrict__ mask) {
    __shared__ float X[64][65];
    __shared__ float Y[64][65];
    __shared__ float tok[64];
    const int bid = blockIdx.x;
    const int h = bid % NHc;
    const int win = (bid / NHc) & 63;
    const int b = bid / (NHc * 64);
    const int wy = win >> 3, wx = win & 7;
    const int tid = threadIdx.x;
    const size_t base = ((size_t)b * NHc + h) * Nc;

    float vreg[4][4];
#pragma unroll
    for (int l = 0; l < 4; l++) {
        int idx = tid + l * 256;
        int t = idx >> 4;
        int dq = (idx & 15) << 2;
        int iy = t >> 3, ix = t & 7;
        int nimg = (wy * 8 + iy) * Wc + wx * 8 + ix;
        size_t off = (base + 1 + nimg) * HDc + dq;
        float4 vq = *reinterpret_cast<const float4*>(&g_q[off]);
        float4 vk = *reinterpret_cast<const float4*>(&g_k[off]);
        float4 vv = *reinterpret_cast<const float4*>(&g_v[off]);
        X[t][dq] = vq.x; X[t][dq + 1] = vq.y; X[t][dq + 2] = vq.z; X[t][dq + 3] = vq.w;
        Y[t][dq] = vk.x; Y[t][dq + 1] = vk.y; Y[t][dq + 2] = vk.z; Y[t][dq + 3] = vk.w;
        vreg[l][0] = vv.x; vreg[l][1] = vv.y; vreg[l][2] = vv.z; vreg[l][3] = vv.w;
    }
    if (tid < 64) {
        int iy = tid >> 3, ix = tid & 7;
        int nimg = (wy * 8 + iy) * Wc + wx * 8 + ix;
        tok[tid] = mask[((size_t)b * HWc + nimg) * Cc];
    }
    __syncthreads();

    const int rg = tid >> 4, cg = tid & 15;
    const int i0 = rg * 4, j0 = cg * 4;
    float s[4][4];
#pragma unroll
    for (int ii = 0; ii < 4; ii++)
#pragma unroll
        for (int jj = 0; jj < 4; jj++) s[ii][jj] = 0.f;

#pragma unroll 8
    for (int d = 0; d < 64; d++) {
        float a[4], bb[4];
#pragma unroll
        for (int ii = 0; ii < 4; ii++) a[ii] = X[i0 + ii][d];
#pragma unroll
        for (int jj = 0; jj < 4; jj++) bb[jj] = Y[j0 + jj][d];
#pragma unroll
        for (int ii = 0; ii < 4; ii++)
#pragma unroll
            for (int jj = 0; jj < 4; jj++)
                s[ii][jj] = fmaf(a[ii], bb[jj], s[ii][jj]);
    }
    float ti[4], tj[4];
#pragma unroll
    for (int ii = 0; ii < 4; ii++) ti[ii] = tok[i0 + ii];
#pragma unroll
    for (int jj = 0; jj < 4; jj++) tj[jj] = tok[j0 + jj];
    __syncthreads();  // all reads of X(q), Y(k) done

    // stash V into X
#pragma unroll
    for (int l = 0; l < 4; l++) {
        int idx = tid + l * 256;
        int t = idx >> 4;
        int dq = (idx & 15) << 2;
        X[t][dq] = vreg[l][0]; X[t][dq + 1] = vreg[l][1];
        X[t][dq + 2] = vreg[l][2]; X[t][dq + 3] = vreg[l][3];
    }
    // softmax per row (16 threads per row; lanes form aligned 16-groups in a warp)
#pragma unroll
    for (int ii = 0; ii < 4; ii++) {
        float mx = -1e30f;
#pragma unroll
        for (int jj = 0; jj < 4; jj++) {
            float val = (ti[ii] * tj[jj] == 0.f) ? NEG_C : s[ii][jj] * SCALEc;
            s[ii][jj] = val;
            mx = fmaxf(mx, val);
        }
#pragma unroll
        for (int o = 8; o >= 1; o >>= 1)
            mx = fmaxf(mx, __shfl_xor_sync(0xffffffffu, mx, o));
        float sum = 0.f;
#pragma unroll
        for (int jj = 0; jj < 4; jj++) {
            float e = expf(s[ii][jj] - mx);
            s[ii][jj] = e;
            sum += e;
        }
#pragma unroll
        for (int o = 8; o >= 1; o >>= 1)
            sum += __shfl_xor_sync(0xffffffffu, sum, o);
        float inv = 1.f / sum;
#pragma unroll
        for (int jj = 0; jj < 4; jj++) Y[i0 + ii][j0 + jj] = s[ii][jj] * inv;
    }
    __syncthreads();

    // O = P @ V
    float o[4][4];
#pragma unroll
    for (int ii = 0; ii < 4; ii++)
#pragma unroll
        for (int jj = 0; jj < 4; jj++) o[ii][jj] = 0.f;
#pragma unroll 8
    for (int k = 0; k < 64; k++) {
        float a[4], bb[4];
#pragma unroll
        for (int ii = 0; ii < 4; ii++) a[ii] = Y[i0 + ii][k];
#pragma unroll
        for (int jj = 0; jj < 4; jj++) bb[jj] = X[k][j0 + jj];
#pragma unroll
        for (int ii = 0; ii < 4; ii++)
#pragma unroll
            for (int jj = 0; jj < 4; jj++)
                o[ii][jj] = fmaf(a[ii], bb[jj], o[ii][jj]);
    }
#pragma unroll
    for (int ii = 0; ii < 4; ii++) {
        int i = i0 + ii;
        int iy = i >> 3, ix = i & 7;
        int nimg = (wy * 8 + iy) * Wc + wx * 8 + ix;
        float4 w = make_float4(o[ii][0], o[ii][1], o[ii][2], o[ii][3]);
        *reinterpret_cast<float4*>(&g_y[((size_t)b * Nc + 1 + nimg) * Cc + h * 64 + j0]) = w;
    }
}

// ---------------------------------------------------------------------------
// Global (cls) attention: one block per (b, h). 4096 keys, HD=64.
// am_g = tok[n] * global_mask[b,h,0,n].
// ---------------------------------------------------------------------------
__global__ __launch_bounds__(256)
void cls_attn(const float* __restrict__ mask, const float* __restrict__ gmask) {
    __shared__ float qsh[64];
    __shared__ float sc[HWc];
    __shared__ float red[256];
    __shared__ float part[4][64];
    const int b = blockIdx.x / NHc;
    const int h = blockIdx.x % NHc;
    const int tid = threadIdx.x;
    const size_t base = ((size_t)b * NHc + h) * Nc;
    if (tid < 64) qsh[tid] = g_q[base * HDc + tid];
    __syncthreads();

    float lmax = -1e30f;
    for (int rep = 0; rep < 16; rep++) {
        int n = rep * 256 + tid;
        const float* kr = &g_k[(base + 1 + n) * HDc];
        float acc = 0.f;
#pragma unroll
        for (int d = 0; d < 64; d++) acc = fmaf(qsh[d], kr[d], acc);
        float tokn = mask[((size_t)b * HWc + n) * Cc];
        float gm = gmask[((size_t)b * NHc + h) * HWc + n];
        float s = (tokn * gm == 0.f) ? NEG_C : acc * SCALEc;
        sc[n] = s;
        lmax = fmaxf(lmax, s);
    }
    red[tid] = lmax;
    __syncthreads();
    for (int st = 128; st > 0; st >>= 1) {
        if (tid < st) red[tid] = fmaxf(red[tid], red[tid + st]);
        __syncthreads();
    }
    float mx = red[0];
    __syncthreads();
    float lsum = 0.f;
    for (int rep = 0; rep < 16; rep++) {
        int n = rep * 256 + tid;
        float e = expf(sc[n] - mx);
        sc[n] = e;
        lsum += e;
    }
    red[tid] = lsum;
    __syncthreads();
    for (int st = 128; st > 0; st >>= 1) {
        if (tid < st) red[tid] += red[tid + st];
        __syncthreads();
    }
    float inv = 1.f / red[0];

    int d = tid & 63, g = tid >> 6;
    float acc = 0.f;
    for (int n = g; n < HWc; n += 4)
        acc = fmaf(sc[n], g_v[(base + 1 + n) * HDc + d], acc);
    part[g][d] = acc;
    __syncthreads();
    if (tid < 64)
        g_y[(size_t)b * Nc * Cc + h * 64 + tid] =
            (part[0][tid] + part[1][tid] + part[2][tid] + part[3][tid]) * inv;
}

// ---------------------------------------------------------------------------
// v_cls = x_cls @ kv_global_w[:, 768:1536]   (k_cls is dead: softmax over NC=1 == 1)
// ---------------------------------------------------------------------------
__global__ __launch_bounds__(256)
void vcls_gemm(const float* __restrict__ kvw) {
    __shared__ float xc[768];
    const int b = blockIdx.x;
    const int tid = threadIdx.x;
#pragma unroll
    for (int l = 0; l < 3; l++)
        xc[tid + l * 256] = g_y[(size_t)b * Nc * Cc + tid + l * 256];
    __syncthreads();
    float acc[3] = {0.f, 0.f, 0.f};
    for (int k = 0; k < 768; k++) {
        float xv = xc[k];
        const float* wr = &kvw[(size_t)k * 1536 + 768];
#pragma unroll
        for (int l = 0; l < 3; l++)
            acc[l] = fmaf(xv, wr[tid + l * 256], acc[l]);
    }
#pragma unroll
    for (int l = 0; l < 3; l++)
        g_vcls[b * Cc + tid + l * 256] = acc[l];
}

// x_img += v_cls broadcast (the entire attn_b stage, since softmax over NC=1 is 1)
__global__ void add_vcls_kernel() {
    constexpr size_t total = (size_t)Bc * HWc * Cc;
    size_t idx = (size_t)blockIdx.x * blockDim.x + threadIdx.x;
    if (idx >= total) return;
    int c = (int)(idx % Cc);
    size_t rem = idx / Cc;
    int n = (int)(rem % HWc);
    int b = (int)(rem / HWc);
    g_y[((size_t)b * Nc + 1 + n) * Cc + c] += g_vcls[b * Cc + c];
}

// ---------------------------------------------------------------------------
extern "C" void kernel_launch(void* const* d_in, const int* in_sizes, int n_in,
                              void* d_out, int out_size) {
    (void)in_sizes; (void)n_in; (void)out_size;
    const float* x      = (const float*)d_in[0];
    const float* mask   = (const float*)d_in[1];
    const float* gmask  = (const float*)d_in[2];
    const float* qkv_w  = (const float*)d_in[3];
    const float* kv_w   = (const float*)d_in[4];
    const float* proj_w = (const float*)d_in[5];
    const float* proj_b = (const float*)d_in[6];
    float* out = (float*)d_out;

    // 1) qkv = x @ qkv_w, scattered into head-major q/k/v
    dim3 g1(2304 / 128, (Mtot + 127) / 128);
    sgemm<2304, 1, false><<<g1, 256>>>(x, qkv_w, nullptr, nullptr);

    // 2) window attention -> g_y image rows
    win_attn<<<Bc * 64 * NHc, 256>>>(mask);

    // 3) cls global attention -> g_y row 0 per batch
    cls_attn<<<Bc * NHc, 256>>>(mask, gmask);

    // 4) v_cls = x_cls @ kv_global_w[:,768:]
    vcls_gemm<<<Bc, 256>>>(kv_w);

    // 5) x_img += v_cls
    constexpr size_t total = (size_t)Bc * HWc * Cc;
    add_vcls_kernel<<<(unsigned)((total + 255) / 256), 256>>>();

    // 6) out = y @ proj_w + proj_b
    dim3 g2(768 / 128, (Mtot + 127) / 128);
    sgemm<768, 0, true><<<g2, 256>>>(nullptr, proj_w, out, proj_b);
}

// round 12
// speedup vs baseline: 1.6085x; 1.0002x over previous
#include <cuda_runtime.h>
#include <math.h>

// Problem constants (fixed by the reference)
constexpr int Bc = 8, Cc = 768, NHc = 12, HDc = 64;
constexpr int Hc = 64, Wc = 64, HWc = 4096, Nc = 4097;   // N = NC + H*W, NC = 1
constexpr int Mtot = Bc * Nc;                            // 32776
constexpr float SCALEc = 0.125f;                         // HD^-0.5
#define NEG_C (-10000.0f)

// Scratch (device globals — allocation-free per harness rules)
__device__ float g_q[(size_t)Bc * NHc * Nc * HDc];
__device__ float g_k[(size_t)Bc * NHc * Nc * HDc];
__device__ float g_v[(size_t)Bc * NHc * Nc * HDc];
__device__ float g_y[(size_t)Bc * Nc * Cc];   // row 0 per batch = x_cls, rows 1.. = x_img
__device__ float g_vcls[Bc * Cc];

// ---------------------------------------------------------------------------
// Tiled SGEMM: C[M x NCOLS] = A[M x 768] @ B[768 x NCOLS]
//   EPI=1: scatter into g_q/g_k/g_v with layout [b, h, n, d]
//   EPI=0: C = acc + bias  (proj)
//   AGY:   A comes from the g_y device global instead of the pointer arg
// 128x128 block tile, BK=16, 256 threads, 8x8 per thread.
// ---------------------------------------------------------------------------
template <int NCOLS, int EPI, bool AGY>
__global__ __launch_bounds__(256)
void sgemm(const float* __restrict__ Ain, const float* __restrict__ Bm,
           float* __restrict__ Cm, const float* __restrict__ bias) {
    const float* A = AGY ? (const float*)g_y : Ain;
    __shared__ float As[16][128];   // transposed: As[k][m]
    __shared__ float Bs[16][128];
    const int tid = threadIdx.x;
    const int m0 = blockIdx.y * 128;
    const int n0 = blockIdx.x * 128;
    const int ty = tid >> 4, tx = tid & 15;

    float acc[8][8];
#pragma unroll
    for (int i = 0; i < 8; i++)
#pragma unroll
        for (int j = 0; j < 8; j++) acc[i][j] = 0.f;

    for (int k0 = 0; k0 < Cc; k0 += 16) {
#pragma unroll
        for (int l = 0; l < 2; l++) {
            int idx = tid + l * 256;
            int row = idx >> 2;
            int kq = (idx & 3) << 2;
            int gr = m0 + row;
            float4 va = make_float4(0.f, 0.f, 0.f, 0.f);
            if (gr < Mtot)
                va = *reinterpret_cast<const float4*>(&A[(size_t)gr * Cc + k0 + kq]);
            As[kq + 0][row] = va.x;
            As[kq + 1][row] = va.y;
            As[kq + 2][row] = va.z;
            As[kq + 3][row] = va.w;
        }
#pragma unroll
        for (int l = 0; l < 2; l++) {
            int idx = tid + l * 256;
            int row = idx >> 5;
            int cq = (idx & 31) << 2;
            *reinterpret_cast<float4*>(&Bs[row][cq]) =
                *reinterpret_cast<const float4*>(&Bm[(size_t)(k0 + row) * NCOLS + n0 + cq]);
        }
        __syncthreads();
#pragma unroll
        for (int kk = 0; kk < 16; kk++) {
            float4 a0 = *reinterpret_cast<const float4*>(&As[kk][ty * 8]);
            float4 a1 = *reinterpret_cast<const float4*>(&As[kk][ty * 8 + 4]);
            float4 b0 = *reinterpret_cast<const float4*>(&Bs[kk][tx * 8]);
            float4 b1 = *reinterpret_cast<const float4*>(&Bs[kk][tx * 8 + 4]);
            float a[8] = {a0.x, a0.y, a0.z, a0.w, a1.x, a1.y, a1.z, a1.w};
            float b[8] = {b0.x, b0.y, b0.z, b0.w, b1.x, b1.y, b1.z, b1.w};
#pragma unroll
            for (int i = 0; i < 8; i++)
#pragma unroll
                for (int j = 0; j < 8; j++)
                    acc[i][j] = fmaf(a[i], b[j], acc[i][j]);
        }
        __syncthreads();
    }

    if (EPI == 1) {
        // All 8 columns of a thread share the same (which, head): c0 % 64 <= 56.
        const int c0 = n0 + tx * 8;
        const int which = c0 / Cc;
        const int within0 = c0 - which * Cc;
        const int h = within0 >> 6;
        const int d0 = within0 & 63;
        float* dst = (which == 0) ? g_q : (which == 1) ? g_k : g_v;
#pragma unroll
        for (int i = 0; i < 8; i++) {
            int r = m0 + ty * 8 + i;
            if (r >= Mtot) continue;
            int bb = r / Nc;
            int nn = r - bb * Nc;
            size_t rowoff = (((size_t)bb * NHc + h) * Nc + nn) * HDc + d0;
#pragma unroll
            for (int j = 0; j < 8; j++) dst[rowoff + j] = acc[i][j];
        }
    } else {
        const int c0 = n0 + tx * 8;
#pragma unroll
        for (int i = 0; i < 8; i++) {
            int r = m0 + ty * 8 + i;
            if (r >= Mtot) continue;
#pragma unroll
            for (int j = 0; j < 8; j++)
                Cm[(size_t)r * NCOLS + c0 + j] = acc[i][j] + bias[c0 + j];
        }
    }
}

// ---------------------------------------------------------------------------
// Window attention: one block per (b, window, head). 64 tokens x 64 dims.
// mask collapses to tok_i * tok_j (mask is a channel-broadcast of tok).
// smem: X (q, later v), Y (k, later P). 4x4 register blocking, 256 threads.
// ---------------------------------------------------------------------------
__global__ __launch_bounds__(256)
void win_attn(const float* __restrict__ mask) {
    __shared__ float X[64][65];
    __shared__ float Y[64][65];
    __shared__ float tok[64];
    const int bid = blockIdx.x;
    const int h = bid % NHc;
    const int win = (bid / NHc) & 63;
    const int b = bid / (NHc * 64);
    const int wy = win >> 3, wx = win & 7;
    const int tid = threadIdx.x;
    const size_t base = ((size_t)b * NHc + h) * Nc;

    float vreg[4][4];
#pragma unroll
    for (int l = 0; l < 4; l++) {
        int idx = tid + l * 256;
        int t = idx >> 4;
        int dq = (idx & 15) << 2;
        int iy = t >> 3, ix = t & 7;
        int nimg = (wy * 8 + iy) * Wc + wx * 8 + ix;
        size_t off = (base + 1 + nimg) * HDc + dq;
        float4 vq = *reinterpret_cast<const float4*>(&g_q[off]);
        float4 vk = *reinterpret_cast<const float4*>(&g_k[off]);
        float4 vv = *reinterpret_cast<const float4*>(&g_v[off]);
        X[t][dq] = vq.x; X[t][dq + 1] = vq.y; X[t][dq + 2] = vq.z; X[t][dq + 3] = vq.w;
        Y[t][dq] = vk.x; Y[t][dq + 1] = vk.y; Y[t][dq + 2] = vk.z; Y[t][dq + 3] = vk.w;
        vreg[l][0] = vv.x; vreg[l][1] = vv.y; vreg[l][2] = vv.z; vreg[l][3] = vv.w;
    }
    if (tid < 64) {
        int iy = tid >> 3, ix = tid & 7;
        int nimg = (wy * 8 + iy) * Wc + wx * 8 + ix;
        tok[tid] = mask[((size_t)b * HWc + nimg) * Cc];
    }
    __syncthreads();

    const int rg = tid >> 4, cg = tid & 15;
    const int i0 = rg * 4, j0 = cg * 4;
    float s[4][4];
#pragma unroll
    for (int ii = 0; ii < 4; ii++)
#pragma unroll
        for (int jj = 0; jj < 4; jj++) s[ii][jj] = 0.f;

#pragma unroll 8
    for (int d = 0; d < 64; d++) {
        float a[4], bb[4];
#pragma unroll
        for (int ii = 0; ii < 4; ii++) a[ii] = X[i0 + ii][d];
#pragma unroll
        for (int jj = 0; jj < 4; jj++) bb[jj] = Y[j0 + jj][d];
#pragma unroll
        for (int ii = 0; ii < 4; ii++)
#pragma unroll
            for (int jj = 0; jj < 4; jj++)
                s[ii][jj] = fmaf(a[ii], bb[jj], s[ii][jj]);
    }
    float ti[4], tj[4];
#pragma unroll
    for (int ii = 0; ii < 4; ii++) ti[ii] = tok[i0 + ii];
#pragma unroll
    for (int jj = 0; jj < 4; jj++) tj[jj] = tok[j0 + jj];
    __syncthreads();  // all reads of X(q), Y(k) done

    // stash V into X
#pragma unroll
    for (int l = 0; l < 4; l++) {
        int idx = tid + l * 256;
        int t = idx >> 4;
        int dq = (idx & 15) << 2;
        X[t][dq] = vreg[l][0]; X[t][dq + 1] = vreg[l][1];
        X[t][dq + 2] = vreg[l][2]; X[t][dq + 3] = vreg[l][3];
    }
    // softmax per row (16 threads per row; lanes form aligned 16-groups in a warp)
#pragma unroll
    for (int ii = 0; ii < 4; ii++) {
        float mx = -1e30f;
#pragma unroll
        for (int jj = 0; jj < 4; jj++) {
            float val = (ti[ii] * tj[jj] == 0.f) ? NEG_C : s[ii][jj] * SCALEc;
            s[ii][jj] = val;
            mx = fmaxf(mx, val);
        }
#pragma unroll
        for (int o = 8; o >= 1; o >>= 1)
            mx = fmaxf(mx, __shfl_xor_sync(0xffffffffu, mx, o));
        float sum = 0.f;
#pragma unroll
        for (int jj = 0; jj < 4; jj++) {
            float e = expf(s[ii][jj] - mx);
            s[ii][jj] = e;
            sum += e;
        }
#pragma unroll
        for (int o = 8; o >= 1; o >>= 1)
            sum += __shfl_xor_sync(0xffffffffu, sum, o);
        float inv = 1.f / sum;
#pragma unroll
        for (int jj = 0; jj < 4; jj++) Y[i0 + ii][j0 + jj] = s[ii][jj] * inv;
    }
    __syncthreads();

    // O = P @ V
    float o[4][4];
#pragma unroll
    for (int ii = 0; ii < 4; ii++)
#pragma unroll
        for (int jj = 0; jj < 4; jj++) o[ii][jj] = 0.f;
#pragma unroll 8
    for (int k = 0; k < 64; k++) {
        float a[4], bb[4];
#pragma unroll
        for (int ii = 0; ii < 4; ii++) a[ii] = Y[i0 + ii][k];
#pragma unroll
        for (int jj = 0; jj < 4; jj++) bb[jj] = X[k][j0 + jj];
#pragma unroll
        for (int ii = 0; ii < 4; ii++)
#pragma unroll
            for (int jj = 0; jj < 4; jj++)
                o[ii][jj] = fmaf(a[ii], bb[jj], o[ii][jj]);
    }
#pragma unroll
    for (int ii = 0; ii < 4; ii++) {
        int i = i0 + ii;
        int iy = i >> 3, ix = i & 7;
        int nimg = (wy * 8 + iy) * Wc + wx * 8 + ix;
        float4 w = make_float4(o[ii][0], o[ii][1], o[ii][2], o[ii][3]);
        *reinterpret_cast<float4*>(&g_y[((size_t)b * Nc + 1 + nimg) * Cc + h * 64 + j0]) = w;
    }
}

// ---------------------------------------------------------------------------
// Global (cls) attention: one block per (b, h). 4096 keys, HD=64.
// am_g = tok[n] * global_mask[b,h,0,n].
// ---------------------------------------------------------------------------
__global__ __launch_bounds__(256)
void cls_attn(const float* __restrict__ mask, const float* __restrict__ gmask) {
    __shared__ float qsh[64];
    __shared__ float sc[HWc];
    __shared__ float red[256];
    __shared__ float part[4][64];
    const int b = blockIdx.x / NHc;
    const int h = blockIdx.x % NHc;
    const int tid = threadIdx.x;
    const size_t base = ((size_t)b * NHc + h) * Nc;
    if (tid < 64) qsh[tid] = g_q[base * HDc + tid];
    __syncthreads();

    float lmax = -1e30f;
    for (int rep = 0; rep < 16; rep++) {
        int n = rep * 256 + tid;
        const float* kr = &g_k[(base + 1 + n) * HDc];
        float acc = 0.f;
#pragma unroll
        for (int d = 0; d < 64; d++) acc = fmaf(qsh[d], kr[d], acc);
        float tokn = mask[((size_t)b * HWc + n) * Cc];
        float gm = gmask[((size_t)b * NHc + h) * HWc + n];
        float s = (tokn * gm == 0.f) ? NEG_C : acc * SCALEc;
        sc[n] = s;
        lmax = fmaxf(lmax, s);
    }
    red[tid] = lmax;
    __syncthreads();
    for (int st = 128; st > 0; st >>= 1) {
        if (tid < st) red[tid] = fmaxf(red[tid], red[tid + st]);
        __syncthreads();
    }
    float mx = red[0];
    __syncthreads();
    float lsum = 0.f;
    for (int rep = 0; rep < 16; rep++) {
        int n = rep * 256 + tid;
        float e = expf(sc[n] - mx);
        sc[n] = e;
        lsum += e;
    }
    red[tid] = lsum;
    __syncthreads();
    for (int st = 128; st > 0; st >>= 1) {
        if (tid < st) red[tid] += red[tid + st];
        __syncthreads();
    }
    float inv = 1.f / red[0];

    int d = tid & 63, g = tid >> 6;
    float acc = 0.f;
    for (int n = g; n < HWc; n += 4)
        acc = fmaf(sc[n], g_v[(base + 1 + n) * HDc + d], acc);
    part[g][d] = acc;
    __syncthreads();
    if (tid < 64)
        g_y[(size_t)b * Nc * Cc + h * 64 + tid] =
            (part[0][tid] + part[1][tid] + part[2][tid] + part[3][tid]) * inv;
}

// ---------------------------------------------------------------------------
// v_cls = x_cls @ kv_global_w[:, 768:1536]   (k_cls is dead: softmax over NC=1 == 1)
// ---------------------------------------------------------------------------
__global__ __launch_bounds__(256)
void vcls_gemm(const float* __restrict__ kvw) {
    __shared__ float xc[768];
    const int b = blockIdx.x;
    const int tid = threadIdx.x;
#pragma unroll
    for (int l = 0; l < 3; l++)
        xc[tid + l * 256] = g_y[(size_t)b * Nc * Cc + tid + l * 256];
    __syncthreads();
    float acc[3] = {0.f, 0.f, 0.f};
    for (int k = 0; k < 768; k++) {
        float xv = xc[k];
        const float* wr = &kvw[(size_t)k * 1536 + 768];
#pragma unroll
        for (int l = 0; l < 3; l++)
            acc[l] = fmaf(xv, wr[tid + l * 256], acc[l]);
    }
#pragma unroll
    for (int l = 0; l < 3; l++)
        g_vcls[b * Cc + tid + l * 256] = acc[l];
}

// x_img += v_cls broadcast (the entire attn_b stage, since softmax over NC=1 is 1)
__global__ void add_vcls_kernel() {
    constexpr size_t total = (size_t)Bc * HWc * Cc;
    size_t idx = (size_t)blockIdx.x * blockDim.x + threadIdx.x;
    if (idx >= total) return;
    int c = (int)(idx % Cc);
    size_t rem = idx / Cc;
    int n = (int)(rem % HWc);
    int b = (int)(rem / HWc);
    g_y[((size_t)b * Nc + 1 + n) * Cc + c] += g_vcls[b * Cc + c];
}

// ---------------------------------------------------------------------------
extern "C" void kernel_launch(void* const* d_in, const int* in_sizes, int n_in,
                              void* d_out, int out_size) {
    (void)in_sizes; (void)n_in; (void)out_size;
    const float* x      = (const float*)d_in[0];
    const float* mask   = (const float*)d_in[1];
    const float* gmask  = (const float*)d_in[2];
    const float* qkv_w  = (const float*)d_in[3];
    const float* kv_w   = (const float*)d_in[4];
    const float* proj_w = (const float*)d_in[5];
    const float* proj_b = (const float*)d_in[6];
    float* out = (float*)d_out;

    // 1) qkv = x @ qkv_w, scattered into head-major q/k/v
    dim3 g1(2304 / 128, (Mtot + 127) / 128);
    sgemm<2304, 1, false><<<g1, 256>>>(x, qkv_w, nullptr, nullptr);

    // 2) window attention -> g_y image rows
    win_attn<<<Bc * 64 * NHc, 256>>>(mask);

    // 3) cls global attention -> g_y row 0 per batch
    cls_attn<<<Bc * NHc, 256>>>(mask, gmask);

    // 4) v_cls = x_cls @ kv_global_w[:,768:]
    vcls_gemm<<<Bc, 256>>>(kv_w);

    // 5) x_img += v_cls
    constexpr size_t total = (size_t)Bc * HWc * Cc;
    add_vcls_kernel<<<(unsigned)((total + 255) / 256), 256>>>();

    // 6) out = y @ proj_w + proj_b
    dim3 g2(768 / 128, (Mtot + 127) / 128);
    sgemm<768, 0, true><<<g2, 256>>>(nullptr, proj_w, out, proj_b);
}